// round 3
// baseline (speedup 1.0000x reference)
#include <cuda_runtime.h>
#include <cuda_bf16.h>
#include <math.h>

// Problem constants
constexpr int NB = 8;
constexpr int L  = 4096;
constexpr int S  = 4096;
constexpr int E  = 256;
constexpr int H  = 8;
constexpr int D  = 32;
constexpr int NL = NB * L;   // 32768
constexpr int NS = NB * S;   // 32768
constexpr float EPS = 1e-6f;

// ---------------- scratch (device globals; no allocation allowed) ----------------
__device__ float g_Qf[(size_t)NL * E];   // masked elu(Q)+1
__device__ float g_Kf[(size_t)NS * E];   // masked elu(K)+1
__device__ float g_Vm[(size_t)NS * E];   // masked V / S
__device__ float g_O [(size_t)NL * E];   // pre-merge output
__device__ float g_KV[(size_t)NB * H * D * D];
__device__ float g_Ksum[(size_t)NB * H * D];
__device__ float g_qm[NL];
__device__ float g_km[NS];
__device__ int   g_mask_mode;            // 0=uint8, 1=int32, 2=float32

// ---------------- mask dtype detection + conversion ----------------
__global__ void detect_mask_kernel(const void* mask) {
    const unsigned char* b = (const unsigned char*)mask;
    int one_off1 = 0;
    int has3f = 0;
    for (int i = 0; i < 256; i++) {
        unsigned char c = b[i];
        if ((i & 3) == 1 && c == 1) one_off1++;
        if (c == 0x3F) has3f = 1;
    }
    g_mask_mode = (one_off1 > 0) ? 0 : (has3f ? 2 : 1);
}

__global__ void convert_mask_kernel(const void* __restrict__ m, float* __restrict__ out, int n) {
    int i = blockIdx.x * blockDim.x + threadIdx.x;
    if (i >= n) return;
    int mode = g_mask_mode;
    float v;
    if (mode == 0)      v = ((const unsigned char*)m)[i] ? 1.f : 0.f;
    else if (mode == 1) v = ((const int*)m)[i]           ? 1.f : 0.f;
    else                v = (((const float*)m)[i] != 0.f) ? 1.f : 0.f;
    out[i] = v;
}

// ---------------- fused GEMM: C = A @ W^T (+bias) with epilogue ----------------
// A: [M, E] row-major, W: [E, E] row-major (C[m,n] = sum_k A[m,k]*W[n,k])
// mode 0: plain    mode 1: (elu(x)+1) * rowmask    mode 2: x * rowmask * scale
#define BM 128
#define BN 128
#define BK 16

__global__ __launch_bounds__(256, 2)
void gemm_fused(const float* __restrict__ A,
                const float* __restrict__ W,
                const float* __restrict__ bias,
                float* __restrict__ C,
                const float* __restrict__ rowmask,
                float scale, int mode)
{
    __shared__ float As[BK][BM + 4];
    __shared__ float Bs[BK][BN + 4];

    const int tid = threadIdx.x;
    const int m0 = blockIdx.y * BM;
    const int n0 = blockIdx.x * BN;
    const int tx = tid & 15;        // 0..15 (N dir)
    const int ty = tid >> 4;        // 0..15 (M dir)

    const int lr = tid >> 2;        // 0..63
    const int lc = (tid & 3) << 2;  // 0,4,8,12

    float acc[8][8];
#pragma unroll
    for (int i = 0; i < 8; i++)
#pragma unroll
        for (int j = 0; j < 8; j++) acc[i][j] = 0.f;

    for (int k0 = 0; k0 < E; k0 += BK) {
        // load A tile (transposed into smem): As[kk][m]
#pragma unroll
        for (int p = 0; p < 2; p++) {
            int r = lr + p * 64;
            float4 v = *(const float4*)&A[(size_t)(m0 + r) * E + k0 + lc];
            As[lc + 0][r] = v.x; As[lc + 1][r] = v.y;
            As[lc + 2][r] = v.z; As[lc + 3][r] = v.w;
        }
        // load W tile: Bs[kk][n] = W[n0+n][k0+kk]
#pragma unroll
        for (int p = 0; p < 2; p++) {
            int r = lr + p * 64;
            float4 v = *(const float4*)&W[(size_t)(n0 + r) * E + k0 + lc];
            Bs[lc + 0][r] = v.x; Bs[lc + 1][r] = v.y;
            Bs[lc + 2][r] = v.z; Bs[lc + 3][r] = v.w;
        }
        __syncthreads();

#pragma unroll
        for (int kk = 0; kk < BK; kk++) {
            float a[8], b[8];
            *(float4*)&a[0] = *(const float4*)&As[kk][ty * 8];
            *(float4*)&a[4] = *(const float4*)&As[kk][ty * 8 + 4];
            *(float4*)&b[0] = *(const float4*)&Bs[kk][tx * 8];
            *(float4*)&b[4] = *(const float4*)&Bs[kk][tx * 8 + 4];
#pragma unroll
            for (int i = 0; i < 8; i++)
#pragma unroll
                for (int j = 0; j < 8; j++)
                    acc[i][j] += a[i] * b[j];
        }
        __syncthreads();
    }

    // epilogue
    float rm[8];
    if (mode != 0) {
#pragma unroll
        for (int i = 0; i < 8; i++) rm[i] = rowmask[m0 + ty * 8 + i];
    }
#pragma unroll
    for (int i = 0; i < 8; i++) {
        size_t m = (size_t)(m0 + ty * 8 + i);
        float out[8];
#pragma unroll
        for (int j = 0; j < 8; j++) {
            int nn = n0 + tx * 8 + j;
            float v = acc[i][j];
            if (bias) v += bias[nn];
            if (mode == 1)      { v = (v > 0.f) ? (v + 1.f) : expf(v); v *= rm[i]; }
            else if (mode == 2) { v *= rm[i] * scale; }
            out[j] = v;
        }
        *(float4*)&C[m * E + n0 + tx * 8]     = make_float4(out[0], out[1], out[2], out[3]);
        *(float4*)&C[m * E + n0 + tx * 8 + 4] = make_float4(out[4], out[5], out[6], out[7]);
    }
}

// ---------------- KV aggregation: KV[n,h,d,v] = sum_s Kf*Vm ; Ksum[n,h,d] ----------------
__global__ __launch_bounds__(256)
void kv_agg_kernel(const float* __restrict__ Kf, const float* __restrict__ Vm)
{
    const int n = blockIdx.x >> 3;
    const int h = blockIdx.x & 7;

    __shared__ float sK[64][40];
    __shared__ float sV[64][40];
    __shared__ float red[4][64][16];

    const int tid = threadIdx.x;
    const int g = tid >> 6;             // s-split group 0..3
    const int t = tid & 63;
    const int db = (t >> 3) << 2;       // d base (0..28 step 4)
    const int vb = (t & 7) << 2;        // v base (0..28 step 4)

    const int lr = tid >> 3;            // 0..31
    const int lc = (tid & 7) << 2;      // 0..28

    float acc[4][4];
#pragma unroll
    for (int i = 0; i < 4; i++)
#pragma unroll
        for (int j = 0; j < 4; j++) acc[i][j] = 0.f;
    float ksum = 0.f;

    const size_t base = (size_t)n * S * E + (size_t)h * D;

    for (int s0 = 0; s0 < S; s0 += 64) {
#pragma unroll
        for (int p = 0; p < 2; p++) {
            int r = lr + p * 32;
            size_t off = base + (size_t)(s0 + r) * E + lc;
            *(float4*)&sK[r][lc] = *(const float4*)&Kf[off];
            *(float4*)&sV[r][lc] = *(const float4*)&Vm[off];
        }
        __syncthreads();

        for (int ss = g; ss < 64; ss += 4) {
            float4 k4 = *(const float4*)&sK[ss][db];
            float4 v4 = *(const float4*)&sV[ss][vb];
            acc[0][0] += k4.x * v4.x; acc[0][1] += k4.x * v4.y; acc[0][2] += k4.x * v4.z; acc[0][3] += k4.x * v4.w;
            acc[1][0] += k4.y * v4.x; acc[1][1] += k4.y * v4.y; acc[1][2] += k4.y * v4.z; acc[1][3] += k4.y * v4.w;
            acc[2][0] += k4.z * v4.x; acc[2][1] += k4.z * v4.y; acc[2][2] += k4.z * v4.z; acc[2][3] += k4.z * v4.w;
            acc[3][0] += k4.w * v4.x; acc[3][1] += k4.w * v4.y; acc[3][2] += k4.w * v4.z; acc[3][3] += k4.w * v4.w;
        }
        if (g == 0 && t < 32) {
#pragma unroll
            for (int ss = 0; ss < 64; ss++) ksum += sK[ss][t];
        }
        __syncthreads();
    }

    // cross-group reduction
#pragma unroll
    for (int jd = 0; jd < 4; jd++)
#pragma unroll
        for (int jv = 0; jv < 4; jv++) red[g][t][jd * 4 + jv] = acc[jd][jv];
    __syncthreads();

    const size_t kvbase = (size_t)((n * H + h) * D) * D;
#pragma unroll
    for (int q = 0; q < 4; q++) {
        int o = tid * 4 + q;
        int d = o >> 5, v = o & 31;
        int tt = ((d >> 2) << 3) | (v >> 2);
        int jj = ((d & 3) << 2) | (v & 3);
        float val = red[0][tt][jj] + red[1][tt][jj] + red[2][tt][jj] + red[3][tt][jj];
        g_KV[kvbase + (size_t)d * D + v] = val;
    }
    if (g == 0 && t < 32) g_Ksum[(size_t)(n * H + h) * D + t] = ksum;
}

// ---------------- attention apply: O = (Qf @ KV) * Z * S ----------------
__global__ __launch_bounds__(256)
void attn_kernel(const float* __restrict__ Qf, float* __restrict__ O)
{
    // grid: NB * H * (L/8); block: 8 warps, one (n,l,h) per warp
    const int bid  = blockIdx.x;
    const int n    = bid >> 12;          // H*(L/8) = 4096 per n
    const int h    = (bid >> 9) & 7;
    const int lgrp = bid & 511;

    __shared__ float sKV[32][32];
    __shared__ float sKs[32];

    const int tid = threadIdx.x;
    const float* kvp = g_KV + (size_t)((n * H + h) * D) * D;
    ((float4*)sKV)[tid] = ((const float4*)kvp)[tid];
    if (tid < 32) sKs[tid] = g_Ksum[(size_t)(n * H + h) * D + tid];
    __syncthreads();

    const int w = tid >> 5, lane = tid & 31;
    const int l = (lgrp << 3) | w;
    const size_t ro = ((size_t)n * L + l) * E + (size_t)h * D;

    float qf = Qf[ro + lane];
    float z = qf * sKs[lane];
#pragma unroll
    for (int o = 16; o; o >>= 1) z += __shfl_xor_sync(0xffffffffu, z, o);
    float zinv = (float)S / (z + EPS);

    float acc = 0.f;
#pragma unroll
    for (int d = 0; d < 32; d++)
        acc += __shfl_sync(0xffffffffu, qf, d) * sKV[d][lane];

    O[ro + lane] = acc * zinv;   // FIX: was O[ro] — all lanes raced on one element
}

// ---------------- launch ----------------
extern "C" void kernel_launch(void* const* d_in, const int* in_sizes, int n_in,
                              void* d_out, int out_size)
{
    const float* q   = (const float*)d_in[0];
    const float* k   = (const float*)d_in[1];
    const float* v   = (const float*)d_in[2];
    const void*  qmask = d_in[3];
    const void*  kmask = d_in[4];
    const float* Wq  = (const float*)d_in[5];
    const float* bq  = (const float*)d_in[6];
    const float* Wk  = (const float*)d_in[7];
    const float* bk  = (const float*)d_in[8];
    const float* Wv  = (const float*)d_in[9];
    const float* bv  = (const float*)d_in[10];
    const float* Wm  = (const float*)d_in[11];
    float* out = (float*)d_out;

    float* g_qm_p; cudaGetSymbolAddress((void**)&g_qm_p, g_qm);
    float* g_km_p; cudaGetSymbolAddress((void**)&g_km_p, g_km);
    float* g_Qf_p; cudaGetSymbolAddress((void**)&g_Qf_p, g_Qf);
    float* g_Kf_p; cudaGetSymbolAddress((void**)&g_Kf_p, g_Kf);
    float* g_Vm_p; cudaGetSymbolAddress((void**)&g_Vm_p, g_Vm);
    float* g_O_p;  cudaGetSymbolAddress((void**)&g_O_p,  g_O);

    // 1) mask dtype detect + convert
    detect_mask_kernel<<<1, 1>>>(qmask);
    convert_mask_kernel<<<(NL + 255) / 256, 256>>>(qmask, g_qm_p, NL);
    convert_mask_kernel<<<(NS + 255) / 256, 256>>>(kmask, g_km_p, NS);

    // 2) fused QKV projections
    dim3 ggrid(E / BN, NL / BM);
    gemm_fused<<<ggrid, 256>>>(q, Wq, bq, g_Qf_p, g_qm_p, 1.0f, 1);            // Qf = (elu+1)*qm
    gemm_fused<<<ggrid, 256>>>(k, Wk, bk, g_Kf_p, g_km_p, 1.0f, 1);            // Kf = (elu+1)*km
    gemm_fused<<<ggrid, 256>>>(v, Wv, bv, g_Vm_p, g_km_p, 1.0f / (float)S, 2); // Vm = V*km/S

    // 3) KV aggregation + Ksum
    kv_agg_kernel<<<NB * H, 256>>>(g_Kf_p, g_Vm_p);

    // 4) attention apply
    attn_kernel<<<NB * H * (L / 8), 256>>>(g_Qf_p, g_O_p);

    // 5) merge projection (no bias)
    gemm_fused<<<ggrid, 256>>>(g_O_p, Wm, nullptr, out, nullptr, 1.0f, 0);
}

// round 4
// speedup vs baseline: 1.9655x; 1.9655x over previous
#include <cuda_runtime.h>
#include <cuda_bf16.h>
#include <math.h>
#include <stdint.h>

// Problem constants
constexpr int NB = 8;
constexpr int L  = 4096;
constexpr int S  = 4096;
constexpr int E  = 256;
constexpr int H  = 8;
constexpr int D  = 32;
constexpr int NL = NB * L;   // 32768
constexpr int NS = NB * S;   // 32768
constexpr float EPS = 1e-6f;
constexpr int KV_SPLIT = 8;

// ---------------- scratch (device globals; no allocation allowed) ----------------
__device__ float g_Qf[(size_t)NL * E];   // masked elu(Q)+1
__device__ float g_Kf[(size_t)NS * E];   // masked elu(K)+1
__device__ float g_Vm[(size_t)NS * E];   // masked V / S
__device__ float g_O [(size_t)NL * E];   // pre-merge output
__device__ float g_KV[(size_t)NB * H * D * D];
__device__ float g_Ksum[(size_t)NB * H * D];
__device__ float g_KVp[KV_SPLIT][(size_t)NB * H * D * D];
__device__ float g_Ksump[KV_SPLIT][(size_t)NB * H * D];
__device__ float g_qm[NL];
__device__ float g_km[NS];
__device__ int   g_mask_mode;            // 0=uint8, 1=int32, 2=float32

// ---------------- mask dtype detection + conversion ----------------
__global__ void detect_mask_kernel(const void* mask) {
    const unsigned char* b = (const unsigned char*)mask;
    int one_off1 = 0;
    int has3f = 0;
    for (int i = 0; i < 256; i++) {
        unsigned char c = b[i];
        if ((i & 3) == 1 && c == 1) one_off1++;
        if (c == 0x3F) has3f = 1;
    }
    g_mask_mode = (one_off1 > 0) ? 0 : (has3f ? 2 : 1);
}

__global__ void convert_mask_kernel(const void* __restrict__ m, float* __restrict__ out, int n) {
    int i = blockIdx.x * blockDim.x + threadIdx.x;
    if (i >= n) return;
    int mode = g_mask_mode;
    float v;
    if (mode == 0)      v = ((const unsigned char*)m)[i] ? 1.f : 0.f;
    else if (mode == 1) v = ((const int*)m)[i]           ? 1.f : 0.f;
    else                v = (((const float*)m)[i] != 0.f) ? 1.f : 0.f;
    out[i] = v;
}

// ---------------- tf32 helpers ----------------
__device__ __forceinline__ float cvt_tf32(float x) {
    uint32_t u;
    asm("cvt.rna.tf32.f32 %0, %1;" : "=r"(u) : "f"(x));
    return __uint_as_float(u);
}

__device__ __forceinline__ void mma_tf32(float (&d)[4], const uint32_t (&a)[4], const uint32_t (&b)[2]) {
    asm volatile(
        "mma.sync.aligned.m16n8k8.row.col.f32.tf32.tf32.f32 "
        "{%0,%1,%2,%3}, {%4,%5,%6,%7}, {%8,%9}, {%0,%1,%2,%3};"
        : "+f"(d[0]), "+f"(d[1]), "+f"(d[2]), "+f"(d[3])
        : "r"(a[0]), "r"(a[1]), "r"(a[2]), "r"(a[3]), "r"(b[0]), "r"(b[1]));
}

// ---------------- tf32 tensor-core GEMM: C = A @ W^T (+bias) with epilogue ----------------
// A: [M, E] row-major, W: [E, E] row-major (C[m,n] = sum_k A[m,k]*W[n,k])
// mode 0: plain    mode 1: (elu(x)+1) * rowmask    mode 2: x * rowmask * scale
#define BM 128
#define BN 128
#define BK 32
#define SSTRIDE 136   // BM + 8; 136 mod 32 = 8 -> conflict-free fragment reads

__global__ __launch_bounds__(256, 2)
void gemm_tf32(const float* __restrict__ A,
               const float* __restrict__ W,
               const float* __restrict__ bias,
               float* __restrict__ C,
               const float* __restrict__ rowmask,
               float scale, int mode)
{
    __shared__ float As[BK][SSTRIDE];
    __shared__ float Bs[BK][SSTRIDE];

    const int tid  = threadIdx.x;
    const int m0   = blockIdx.y * BM;
    const int n0   = blockIdx.x * BN;
    const int wid  = tid >> 5;
    const int lane = tid & 31;
    const int wm   = (wid & 1) * 64;   // warp M offset (2 warps in M)
    const int wn   = (wid >> 1) * 32;  // warp N offset (4 warps in N)
    const int g    = lane >> 2;        // groupID (0..7)
    const int tg   = lane & 3;         // thread-in-group (0..3)

    // loader indices: thread loads float4 at (row = lrow + 32p, cols lcol..lcol+3)
    const int lrow = tid >> 3;         // 0..31
    const int lcol = (tid & 7) * 4;    // 0,4,...,28
    const int swst = ((lcol >> 2) & 7) << 2;  // store swizzle (same for j=0..3)

    float acc[4][4][4];
#pragma unroll
    for (int i = 0; i < 4; i++)
#pragma unroll
        for (int j = 0; j < 4; j++)
#pragma unroll
            for (int r = 0; r < 4; r++) acc[i][j][r] = 0.f;

    for (int k0 = 0; k0 < E; k0 += BK) {
        // ---- load + transpose + cvt into swizzled smem ----
#pragma unroll
        for (int p = 0; p < 4; p++) {
            int r = lrow + p * 32;
            int mc = r ^ swst;
            float4 va = *(const float4*)&A[(size_t)(m0 + r) * E + k0 + lcol];
            As[lcol + 0][mc] = cvt_tf32(va.x);
            As[lcol + 1][mc] = cvt_tf32(va.y);
            As[lcol + 2][mc] = cvt_tf32(va.z);
            As[lcol + 3][mc] = cvt_tf32(va.w);
            float4 vb = *(const float4*)&W[(size_t)(n0 + r) * E + k0 + lcol];
            Bs[lcol + 0][mc] = cvt_tf32(vb.x);
            Bs[lcol + 1][mc] = cvt_tf32(vb.y);
            Bs[lcol + 2][mc] = cvt_tf32(vb.z);
            Bs[lcol + 3][mc] = cvt_tf32(vb.w);
        }
        __syncthreads();

        // ---- 4 k-steps of m16n8k8 ----
#pragma unroll
        for (int kk = 0; kk < BK; kk += 8) {
            const int kr1 = kk + tg;       // rows for a0/a1/b0
            const int kr2 = kk + tg + 4;   // rows for a2/a3/b1
            const int sw1 = ((kr1 >> 2) & 7) << 2;
            const int sw2 = ((kr2 >> 2) & 7) << 2;

            uint32_t a[4][4];
#pragma unroll
            for (int i = 0; i < 4; i++) {
                int mrow = wm + i * 16;
                a[i][0] = __float_as_uint(As[kr1][(mrow + g    ) ^ sw1]);
                a[i][1] = __float_as_uint(As[kr1][(mrow + g + 8) ^ sw1]);
                a[i][2] = __float_as_uint(As[kr2][(mrow + g    ) ^ sw2]);
                a[i][3] = __float_as_uint(As[kr2][(mrow + g + 8) ^ sw2]);
            }
            uint32_t b[4][2];
#pragma unroll
            for (int j = 0; j < 4; j++) {
                int ncol = wn + j * 8;
                b[j][0] = __float_as_uint(Bs[kr1][(ncol + g) ^ sw1]);
                b[j][1] = __float_as_uint(Bs[kr2][(ncol + g) ^ sw2]);
            }
#pragma unroll
            for (int i = 0; i < 4; i++)
#pragma unroll
                for (int j = 0; j < 4; j++)
                    mma_tf32(acc[i][j], a[i], b[j]);
        }
        __syncthreads();
    }

    // ---- epilogue ----
#pragma unroll
    for (int i = 0; i < 4; i++) {
        const int r0 = m0 + wm + i * 16 + g;
        const int r1 = r0 + 8;
        float rm0 = 0.f, rm1 = 0.f;
        if (mode != 0) { rm0 = rowmask[r0]; rm1 = rowmask[r1]; }
#pragma unroll
        for (int j = 0; j < 4; j++) {
            const int col = n0 + wn + j * 8 + 2 * tg;
            float b0 = 0.f, b1 = 0.f;
            if (bias) { b0 = bias[col]; b1 = bias[col + 1]; }
            float v0 = acc[i][j][0] + b0;
            float v1 = acc[i][j][1] + b1;
            float v2 = acc[i][j][2] + b0;
            float v3 = acc[i][j][3] + b1;
            if (mode == 1) {
                v0 = ((v0 > 0.f) ? (v0 + 1.f) : expf(v0)) * rm0;
                v1 = ((v1 > 0.f) ? (v1 + 1.f) : expf(v1)) * rm0;
                v2 = ((v2 > 0.f) ? (v2 + 1.f) : expf(v2)) * rm1;
                v3 = ((v3 > 0.f) ? (v3 + 1.f) : expf(v3)) * rm1;
            } else if (mode == 2) {
                v0 *= rm0 * scale; v1 *= rm0 * scale;
                v2 *= rm1 * scale; v3 *= rm1 * scale;
            }
            *(float2*)&C[(size_t)r0 * E + col] = make_float2(v0, v1);
            *(float2*)&C[(size_t)r1 * E + col] = make_float2(v2, v3);
        }
    }
}

// ---------------- KV aggregation (s-split): partial KV[n,h,d,v], Ksum[n,h,d] ----------------
__global__ __launch_bounds__(256)
void kv_agg_kernel(const float* __restrict__ Kf, const float* __restrict__ Vm)
{
    const int n = blockIdx.x >> 3;
    const int h = blockIdx.x & 7;
    const int split = blockIdx.y;
    const int sbeg = split * (S / KV_SPLIT);
    const int send = sbeg + (S / KV_SPLIT);

    __shared__ float sK[64][40];
    __shared__ float sV[64][40];
    __shared__ float red[4][64][16];

    const int tid = threadIdx.x;
    const int g = tid >> 6;             // s-split group 0..3
    const int t = tid & 63;
    const int db = (t >> 3) << 2;       // d base
    const int vb = (t & 7) << 2;        // v base

    const int lr = tid >> 3;            // 0..31
    const int lc = (tid & 7) << 2;      // 0..28

    float acc[4][4];
#pragma unroll
    for (int i = 0; i < 4; i++)
#pragma unroll
        for (int j = 0; j < 4; j++) acc[i][j] = 0.f;
    float ksum = 0.f;

    const size_t base = (size_t)n * S * E + (size_t)h * D;

    for (int s0 = sbeg; s0 < send; s0 += 64) {
#pragma unroll
        for (int p = 0; p < 2; p++) {
            int r = lr + p * 32;
            size_t off = base + (size_t)(s0 + r) * E + lc;
            *(float4*)&sK[r][lc] = *(const float4*)&Kf[off];
            *(float4*)&sV[r][lc] = *(const float4*)&Vm[off];
        }
        __syncthreads();

        for (int ss = g; ss < 64; ss += 4) {
            float4 k4 = *(const float4*)&sK[ss][db];
            float4 v4 = *(const float4*)&sV[ss][vb];
            acc[0][0] += k4.x * v4.x; acc[0][1] += k4.x * v4.y; acc[0][2] += k4.x * v4.z; acc[0][3] += k4.x * v4.w;
            acc[1][0] += k4.y * v4.x; acc[1][1] += k4.y * v4.y; acc[1][2] += k4.y * v4.z; acc[1][3] += k4.y * v4.w;
            acc[2][0] += k4.z * v4.x; acc[2][1] += k4.z * v4.y; acc[2][2] += k4.z * v4.z; acc[2][3] += k4.z * v4.w;
            acc[3][0] += k4.w * v4.x; acc[3][1] += k4.w * v4.y; acc[3][2] += k4.w * v4.z; acc[3][3] += k4.w * v4.w;
        }
        if (g == 0 && t < 32) {
#pragma unroll
            for (int ss = 0; ss < 64; ss++) ksum += sK[ss][t];
        }
        __syncthreads();
    }

    // cross-group reduction
#pragma unroll
    for (int jd = 0; jd < 4; jd++)
#pragma unroll
        for (int jv = 0; jv < 4; jv++) red[g][t][jd * 4 + jv] = acc[jd][jv];
    __syncthreads();

    const size_t kvbase = (size_t)((n * H + h) * D) * D;
#pragma unroll
    for (int q = 0; q < 4; q++) {
        int o = tid * 4 + q;
        int d = o >> 5, v = o & 31;
        int tt = ((d >> 2) << 3) | (v >> 2);
        int jj = ((d & 3) << 2) | (v & 3);
        float val = red[0][tt][jj] + red[1][tt][jj] + red[2][tt][jj] + red[3][tt][jj];
        g_KVp[split][kvbase + (size_t)d * D + v] = val;
    }
    if (g == 0 && t < 32) g_Ksump[split][(size_t)(n * H + h) * D + t] = ksum;
}

// ---------------- KV partial reduction ----------------
__global__ void kv_reduce_kernel() {
    const int NKV = NB * H * D * D;     // 65536
    const int NKS = NB * H * D;         // 2048
    int i = blockIdx.x * blockDim.x + threadIdx.x;
    if (i < NKV) {
        float s = 0.f;
#pragma unroll
        for (int p = 0; p < KV_SPLIT; p++) s += g_KVp[p][i];
        g_KV[i] = s;
    } else if (i < NKV + NKS) {
        int j = i - NKV;
        float s = 0.f;
#pragma unroll
        for (int p = 0; p < KV_SPLIT; p++) s += g_Ksump[p][j];
        g_Ksum[j] = s;
    }
}

// ---------------- attention apply: O = (Qf @ KV) * Z * S ----------------
__global__ __launch_bounds__(256)
void attn_kernel(const float* __restrict__ Qf, float* __restrict__ O)
{
    const int bid  = blockIdx.x;
    const int n    = bid >> 12;
    const int h    = (bid >> 9) & 7;
    const int lgrp = bid & 511;

    __shared__ float sKV[32][32];
    __shared__ float sKs[32];

    const int tid = threadIdx.x;
    const float* kvp = g_KV + (size_t)((n * H + h) * D) * D;
    ((float4*)sKV)[tid] = ((const float4*)kvp)[tid];
    if (tid < 32) sKs[tid] = g_Ksum[(size_t)(n * H + h) * D + tid];
    __syncthreads();

    const int w = tid >> 5, lane = tid & 31;
    const int l = (lgrp << 3) | w;
    const size_t ro = ((size_t)n * L + l) * E + (size_t)h * D;

    float qf = Qf[ro + lane];
    float z = qf * sKs[lane];
#pragma unroll
    for (int o = 16; o; o >>= 1) z += __shfl_xor_sync(0xffffffffu, z, o);
    float zinv = (float)S / (z + EPS);

    float acc = 0.f;
#pragma unroll
    for (int d = 0; d < 32; d++)
        acc += __shfl_sync(0xffffffffu, qf, d) * sKV[d][lane];

    O[ro + lane] = acc * zinv;
}

// ---------------- launch ----------------
extern "C" void kernel_launch(void* const* d_in, const int* in_sizes, int n_in,
                              void* d_out, int out_size)
{
    const float* q   = (const float*)d_in[0];
    const float* k   = (const float*)d_in[1];
    const float* v   = (const float*)d_in[2];
    const void*  qmask = d_in[3];
    const void*  kmask = d_in[4];
    const float* Wq  = (const float*)d_in[5];
    const float* bq  = (const float*)d_in[6];
    const float* Wk  = (const float*)d_in[7];
    const float* bk  = (const float*)d_in[8];
    const float* Wv  = (const float*)d_in[9];
    const float* bv  = (const float*)d_in[10];
    const float* Wm  = (const float*)d_in[11];
    float* out = (float*)d_out;

    float* g_qm_p; cudaGetSymbolAddress((void**)&g_qm_p, g_qm);
    float* g_km_p; cudaGetSymbolAddress((void**)&g_km_p, g_km);
    float* g_Qf_p; cudaGetSymbolAddress((void**)&g_Qf_p, g_Qf);
    float* g_Kf_p; cudaGetSymbolAddress((void**)&g_Kf_p, g_Kf);
    float* g_Vm_p; cudaGetSymbolAddress((void**)&g_Vm_p, g_Vm);
    float* g_O_p;  cudaGetSymbolAddress((void**)&g_O_p,  g_O);

    // 1) mask dtype detect + convert
    detect_mask_kernel<<<1, 1>>>(qmask);
    convert_mask_kernel<<<(NL + 255) / 256, 256>>>(qmask, g_qm_p, NL);
    convert_mask_kernel<<<(NS + 255) / 256, 256>>>(kmask, g_km_p, NS);

    // 2) fused QKV projections (tf32 tensor cores)
    dim3 ggrid(E / BN, NL / BM);
    gemm_tf32<<<ggrid, 256>>>(q, Wq, bq, g_Qf_p, g_qm_p, 1.0f, 1);            // Qf = (elu+1)*qm
    gemm_tf32<<<ggrid, 256>>>(k, Wk, bk, g_Kf_p, g_km_p, 1.0f, 1);            // Kf = (elu+1)*km
    gemm_tf32<<<ggrid, 256>>>(v, Wv, bv, g_Vm_p, g_km_p, 1.0f / (float)S, 2); // Vm = V*km/S

    // 3) KV aggregation (s-split) + reduction
    dim3 kvgrid(NB * H, KV_SPLIT);
    kv_agg_kernel<<<kvgrid, 256>>>(g_Kf_p, g_Vm_p);
    kv_reduce_kernel<<<(NB * H * D * D + NB * H * D + 255) / 256, 256>>>();

    // 4) attention apply
    attn_kernel<<<NB * H * (L / 8), 256>>>(g_Qf_p, g_O_p);

    // 5) merge projection (no bias)
    gemm_tf32<<<ggrid, 256>>>(g_O_p, Wm, nullptr, out, nullptr, 1.0f, 0);
}